// round 3
// baseline (speedup 1.0000x reference)
#include <cuda_runtime.h>

// Problem constants
#define Bb 4
#define Ss 128
#define Dd 768
#define Hh 768
#define MT (Bb * Ss)   // 512 rows for each projection GEMM

// Scratch for projected activations (allocation-free rule: __device__ globals)
__device__ float g_ha[MT * Hh];   // a @ W1[:D] + b1
__device__ float g_hb[MT * Hh];   // b @ W1[D:]

typedef unsigned long long u64;

// ---- packed f32x2 helpers (sm_103a FFMA2 path, only reachable via PTX) ----
static __device__ __forceinline__ u64 pk_dup(float x) {
    u64 r; asm("mov.b64 %0, {%1, %1};" : "=l"(r) : "f"(x)); return r;
}
static __device__ __forceinline__ u64 pk2(float lo, float hi) {
    u64 r; asm("mov.b64 %0, {%1, %2};" : "=l"(r) : "f"(lo), "f"(hi)); return r;
}
static __device__ __forceinline__ void fma2(u64& d, u64 a, u64 b) {
    asm("fma.rn.f32x2 %0, %1, %2, %0;" : "+l"(d) : "l"(a), "l"(b));
}
static __device__ __forceinline__ void upk(u64 v, float& lo, float& hi) {
    asm("mov.b64 {%0, %1}, %2;" : "=f"(lo), "=f"(hi) : "l"(v));
}

// ============================================================================
// Stage 1: ha = a @ W1[:768] + b1 ; hb = b @ W1[768:]
// Tiled fp32 GEMM, BM=64 BN=32 BK=16, 256 threads, TM=4 TN=2 per thread,
// accumulators packed f32x2 along M (A stored k-major-transposed in smem so
// one LDS.128 yields two packed M-pairs with zero pack cost).
// grid = (512/64, 768/32, 2) = (8, 24, 2) = 384 CTAs
// ============================================================================
#define BM 64
#define BN 32
#define BK 16
#define PA 68   // padded pitch for transposed A tile (keeps 16B align, breaks conflicts)

__global__ __launch_bounds__(256) void proj_kernel(
    const float* __restrict__ a, const float* __restrict__ b,
    const float* __restrict__ W1, const float* __restrict__ b1)
{
    __shared__ float As[BK][PA];   // As[k][m]
    __shared__ float Ws[BK][BN];   // Ws[k][n]

    const int z = blockIdx.z;
    const float* __restrict__ X  = z ? b : a;
    const float* __restrict__ Wg = W1 + (size_t)z * Dd * Hh;
    float* __restrict__ Cg       = z ? g_hb : g_ha;

    const int tid    = threadIdx.x;
    const int m_tile = blockIdx.x * BM;
    const int n_tile = blockIdx.y * BN;

    // global-load mapping
    const int lm  = tid >> 2;          // 0..63  (A row)
    const int lk4 = (tid & 3) << 2;    // 0,4,8,12 (A k-offset, float4)
    const int wk  = tid >> 4;          // 0..15  (W k-row)
    const int wn  = (tid & 15) << 1;   // 0..30  (W n-offset, float2)

    // compute mapping: 4 rows x 2 cols per thread
    const int n0 = (tid & 15) << 1;
    const int m0 = (tid >> 4) << 2;

    const float* Xp = X  + (size_t)(m_tile + lm) * Dd + lk4;
    const float* Wp = Wg + (size_t)wk * Hh + n_tile + wn;

    u64 acc00 = 0, acc01 = 0, acc10 = 0, acc11 = 0;  // acc[mpair][n]

    // prefetch k-block 0
    float4 av = *reinterpret_cast<const float4*>(Xp);
    float2 wv = *reinterpret_cast<const float2*>(Wp);

    for (int k0 = 0; k0 < Dd; k0 += BK) {
        __syncthreads();
        As[lk4 + 0][lm] = av.x;
        As[lk4 + 1][lm] = av.y;
        As[lk4 + 2][lm] = av.z;
        As[lk4 + 3][lm] = av.w;
        *reinterpret_cast<float2*>(&Ws[wk][wn]) = wv;
        __syncthreads();
        if (k0 + BK < Dd) {   // prefetch next block; latency hidden by compute below
            av = *reinterpret_cast<const float4*>(Xp + k0 + BK);
            wv = *reinterpret_cast<const float2*>(Wp + (size_t)(k0 + BK) * Hh);
        }
        #pragma unroll
        for (int kk = 0; kk < BK; kk++) {
            float4 a4 = *reinterpret_cast<const float4*>(&As[kk][m0]);  // rows m0..m0+3
            float2 w2 = *reinterpret_cast<const float2*>(&Ws[kk][n0]);  // cols n0,n0+1
            u64 ap0 = pk2(a4.x, a4.y);
            u64 ap1 = pk2(a4.z, a4.w);
            u64 wd0 = pk_dup(w2.x);
            u64 wd1 = pk_dup(w2.y);
            fma2(acc00, ap0, wd0);
            fma2(acc01, ap0, wd1);
            fma2(acc10, ap1, wd0);
            fma2(acc11, ap1, wd1);
        }
    }

    float c00l, c00h, c01l, c01h, c10l, c10h, c11l, c11h;
    upk(acc00, c00l, c00h);
    upk(acc01, c01l, c01h);
    upk(acc10, c10l, c10h);
    upk(acc11, c11l, c11h);

    float bias0 = 0.f, bias1 = 0.f;
    if (z == 0) { bias0 = b1[n_tile + n0]; bias1 = b1[n_tile + n0 + 1]; }

    float* Cp = Cg + (size_t)(m_tile + m0) * Hh + n_tile + n0;
    *reinterpret_cast<float2*>(Cp         ) = make_float2(c00l + bias0, c01l + bias1);
    *reinterpret_cast<float2*>(Cp +     Hh) = make_float2(c00h + bias0, c01h + bias1);
    *reinterpret_cast<float2*>(Cp + 2 * Hh) = make_float2(c10l + bias0, c11l + bias1);
    *reinterpret_cast<float2*>(Cp + 3 * Hh) = make_float2(c10h + bias0, c11h + bias1);
}

// ============================================================================
// Stage 2: out[b,i,j,:] = relu(ha[b,i,:] + hb[b,j,:]) @ W2 + b2
// Never materializes the (B,S,S,H) tensor. CTA = (16 i-rows) x (32 j-rows),
// h streamed in chunks of 128 through smem. 256 threads, each owns (i, j) and
// (i, j+16). Per (pair,h): FADD + FFMA2 (fma pipe), FMNMX + dup-MOV (alu pipe);
// one FFMA2 produces both outputs o=0,1.
// grid = (128/16, 128/32, 4) = (8, 4, 4) = 128 CTAs
// ============================================================================
#define TI 16
#define TJ 32
#define HC 128
#define PP 132  // padded pitch (16B-aligned rows, stride-4 banks -> <=2-way conflicts)

__global__ __launch_bounds__(256) void pair_kernel(
    const float* __restrict__ W2, const float* __restrict__ b2,
    float2* __restrict__ out)
{
    __shared__ float sha[TI][PP];
    __shared__ float shb[TJ][PP];
    __shared__ u64   sw2[HC];      // packed (W2[h,0], W2[h,1])

    const int tid = threadIdx.x;
    const int bi = blockIdx.x, bj = blockIdx.y, bb = blockIdx.z;

    const int li = tid >> 4;   // 0..15 : i within tile
    const int lj = tid & 15;   // j and j+16 within tile

    const float* haBase = g_ha + (size_t)(bb * Ss + bi * TI) * Hh;
    const float* hbBase = g_hb + (size_t)(bb * Ss + bj * TJ) * Hh;

    u64 accA = 0, accB = 0;

    float4 va[2], vb[4], vw;

    // prefetch chunk 0
    {
        #pragma unroll
        for (int r = 0; r < 2; r++) {
            int idx = r * 256 + tid;
            va[r] = *reinterpret_cast<const float4*>(
                haBase + (size_t)(idx >> 5) * Hh + ((idx & 31) << 2));
        }
        #pragma unroll
        for (int r = 0; r < 4; r++) {
            int idx = r * 256 + tid;
            vb[r] = *reinterpret_cast<const float4*>(
                hbBase + (size_t)(idx >> 5) * Hh + ((idx & 31) << 2));
        }
        if (tid < 64) vw = *reinterpret_cast<const float4*>(W2 + tid * 4);
    }

    for (int h0 = 0; h0 < Hh; h0 += HC) {
        __syncthreads();
        #pragma unroll
        for (int r = 0; r < 2; r++) {
            int idx = r * 256 + tid;
            *reinterpret_cast<float4*>(&sha[idx >> 5][(idx & 31) << 2]) = va[r];
        }
        #pragma unroll
        for (int r = 0; r < 4; r++) {
            int idx = r * 256 + tid;
            *reinterpret_cast<float4*>(&shb[idx >> 5][(idx & 31) << 2]) = vb[r];
        }
        if (tid < 64) *reinterpret_cast<float4*>(&sw2[tid * 2]) = vw;
        __syncthreads();

        if (h0 + HC < Hh) {   // prefetch next chunk, hidden under compute
            int hn = h0 + HC;
            #pragma unroll
            for (int r = 0; r < 2; r++) {
                int idx = r * 256 + tid;
                va[r] = *reinterpret_cast<const float4*>(
                    haBase + (size_t)(idx >> 5) * Hh + hn + ((idx & 31) << 2));
            }
            #pragma unroll
            for (int r = 0; r < 4; r++) {
                int idx = r * 256 + tid;
                vb[r] = *reinterpret_cast<const float4*>(
                    hbBase + (size_t)(idx >> 5) * Hh + hn + ((idx & 31) << 2));
            }
            if (tid < 64) vw = *reinterpret_cast<const float4*>(W2 + 2 * hn + tid * 4);
        }

        #pragma unroll 8
        for (int c = 0; c < HC; c += 4) {
            float4 xa  = *reinterpret_cast<const float4*>(&sha[li][c]);
            float4 xb0 = *reinterpret_cast<const float4*>(&shb[lj][c]);
            float4 xb1 = *reinterpret_cast<const float4*>(&shb[lj + 16][c]);
            u64 w0 = sw2[c], w1 = sw2[c + 1], w2v = sw2[c + 2], w3 = sw2[c + 3];
            float sA, sB;
            // interleave the two accumulator chains to cover FFMA2 latency
            sA = fmaxf(xa.x + xb0.x, 0.f); sB = fmaxf(xa.x + xb1.x, 0.f);
            fma2(accA, pk_dup(sA), w0);    fma2(accB, pk_dup(sB), w0);
            sA = fmaxf(xa.y + xb0.y, 0.f); sB = fmaxf(xa.y + xb1.y, 0.f);
            fma2(accA, pk_dup(sA), w1);    fma2(accB, pk_dup(sB), w1);
            sA = fmaxf(xa.z + xb0.z, 0.f); sB = fmaxf(xa.z + xb1.z, 0.f);
            fma2(accA, pk_dup(sA), w2v);   fma2(accB, pk_dup(sB), w2v);
            sA = fmaxf(xa.w + xb0.w, 0.f); sB = fmaxf(xa.w + xb1.w, 0.f);
            fma2(accA, pk_dup(sA), w3);    fma2(accB, pk_dup(sB), w3);
        }
    }

    float aAl, aAh, aBl, aBh;
    upk(accA, aAl, aAh);
    upk(accB, aBl, aBh);
    const float b20 = b2[0], b21 = b2[1];

    size_t base = ((size_t)bb * Ss + bi * TI + li) * Ss + bj * TJ + lj;
    out[base]      = make_float2(aAl + b20, aAh + b21);
    out[base + 16] = make_float2(aBl + b20, aBh + b21);
}

// ============================================================================
// launch
// ============================================================================
extern "C" void kernel_launch(void* const* d_in, const int* in_sizes, int n_in,
                              void* d_out, int out_size)
{
    // Defensive input mapping by element count (robust to metadata ordering):
    // a,b: 393216 ; W1: 1179648 ; b1: 768 ; W2: 1536 ; b2: 2
    const float *a = nullptr, *b = nullptr, *W1 = nullptr, *b1 = nullptr,
                *W2 = nullptr, *b2 = nullptr;
    for (int i = 0; i < n_in; i++) {
        const float* p = (const float*)d_in[i];
        switch (in_sizes[i]) {
            case MT * Dd:      if (!a) a = p; else b = p; break;  // a first, then b
            case 2 * Dd * Hh:  W1 = p; break;
            case Hh:           b1 = p; break;
            case Hh * 2:       W2 = p; break;
            case 2:            b2 = p; break;
            default: break;
        }
    }

    dim3 g1(MT / BM, Hh / BN, 2);        // (8, 24, 2)
    proj_kernel<<<g1, 256>>>(a, b, W1, b1);

    dim3 g2(Ss / TI, Ss / TJ, Bb);       // (8, 4, 4)
    pair_kernel<<<g2, 256>>>(W2, b2, (float2*)d_out);

    (void)out_size;
}